// round 1
// baseline (speedup 1.0000x reference)
#include <cuda_runtime.h>
#include <math.h>

#define QLEN 1024
#define MLEN 1024
#define KLEN 2048
#define BSZ  4
#define NL   12
#define NH   8
#define DHD  64
#define DM   512
#define DI   2048
#define NV   10000
#define HD   512      // NH*DHD
#define QKV  1536     // 3*HD

// ---------------- scratch (device globals; no allocations) ----------------
__device__ float g_h   [QLEN*BSZ*DM];
__device__ float g_cat [KLEN*BSZ*DM];
__device__ float g_heads[KLEN*BSZ*QKV];
__device__ float g_r   [KLEN*DM];
__device__ float g_rhk [KLEN*HD];
__device__ float g_ac  [(size_t)QLEN*KLEN*BSZ*NH];   // scores -> probs
__device__ float g_bd  [(size_t)QLEN*KLEN*BSZ*NH];   // raw BD (pre rel-shift)
__device__ float g_vec [QLEN*BSZ*HD];
__device__ float g_tmp [QLEN*BSZ*DM];
__device__ float g_ff  [QLEN*BSZ*DI];

// ---------------- embedding ----------------
__global__ void k_embed(const int* __restrict__ x, const float* __restrict__ emb,
                        float* __restrict__ h)
{
    int idx = blockIdx.x * blockDim.x + threadIdx.x;
    if (idx >= QLEN*BSZ*DM) return;
    int d = idx & (DM-1);
    int b = (idx >> 9) & 3;
    int i = idx >> 11;
    int tok = x[i*BSZ + b];
    h[idx] = emb[(size_t)tok*DM + d] * 22.627416997969522f;  // sqrt(512)
}

// ---------------- positional embedding r[k, d] ----------------
__global__ void k_posemb(float* __restrict__ r)
{
    int idx = blockIdx.x * blockDim.x + threadIdx.x;
    if (idx >= KLEN*DM) return;
    int d = idx & (DM-1);
    int k = idx >> 9;
    double pos = (double)(KLEN - 1 - k);
    int t = (d < 256) ? d : d - 256;
    double f = exp(-(double)t * (log(10000.0) / 256.0));
    double a = pos * f;
    r[idx] = (float)((d < 256) ? sin(a) : cos(a));
}

// ---------------- generic SGEMM: C[M,N] = A[M,K] * B[N,K]^T (+bias)(+relu) ----------------
// epi: 0 = none, 1 = +bias, 2 = +bias then relu
#define BM 128
#define BN 128
#define BK 16
__global__ __launch_bounds__(256)
void k_sgemm(const float* __restrict__ A, const float* __restrict__ B,
             const float* __restrict__ bias, float* __restrict__ C,
             int M, int N, int K, int epi)
{
    __shared__ float As[BK][BM+4];
    __shared__ float Bs[BK][BN+4];
    int tid = threadIdx.x;
    int m0 = blockIdx.y * BM;
    int n0 = blockIdx.x * BN;
    int tx = tid & 15, ty = tid >> 4;
    float acc[8][8] = {};

    for (int k0 = 0; k0 < K; k0 += BK) {
        #pragma unroll
        for (int i = 0; i < 8; i++) {
            int idx = tid + i*256;
            int rrow = idx / BK, cc = idx % BK;
            int gm = m0 + rrow;
            int gn = n0 + rrow;
            As[cc][rrow] = (gm < M) ? A[(size_t)gm*K + k0 + cc] : 0.f;
            Bs[cc][rrow] = (gn < N) ? B[(size_t)gn*K + k0 + cc] : 0.f;
        }
        __syncthreads();
        #pragma unroll
        for (int kk = 0; kk < BK; kk++) {
            float a[8], b[8];
            #pragma unroll
            for (int i = 0; i < 8; i++) a[i] = As[kk][ty*8+i];
            #pragma unroll
            for (int j = 0; j < 8; j++) b[j] = Bs[kk][tx*8+j];
            #pragma unroll
            for (int i = 0; i < 8; i++)
                #pragma unroll
                for (int j = 0; j < 8; j++)
                    acc[i][j] += a[i]*b[j];
        }
        __syncthreads();
    }
    #pragma unroll
    for (int i = 0; i < 8; i++) {
        int gm = m0 + ty*8 + i;
        if (gm >= M) continue;
        #pragma unroll
        for (int j = 0; j < 8; j++) {
            int gn = n0 + tx*8 + j;
            if (gn >= N) continue;
            float v = acc[i][j];
            if (epi >= 1) v += bias[gn];
            if (epi == 2) v = fmaxf(v, 0.f);
            C[(size_t)gm*N + gn] = v;
        }
    }
}

// ---------------- attention QK: out[bh][i][j] = sum_d (q[i]+bias)[d] * B[j][d] ----------------
// AC: Bbase = heads + HD   (k section), Brow = BSZ*QKV, Bbst = QKV
// BD: Bbase = rhk,                      Brow = HD,      Bbst = 0
__global__ __launch_bounds__(256)
void k_attn_qk(const float* __restrict__ heads, const float* __restrict__ Bbase,
               const float* __restrict__ bias, float* __restrict__ out,
               int Brow, int Bbst)
{
    __shared__ float Qs[64][65];
    __shared__ float Ks[64][65];
    int bh = blockIdx.z, b = bh >> 3, hh = bh & 7;
    int i0 = blockIdx.y << 6, j0 = blockIdx.x << 6;
    int tid = threadIdx.x, tx = tid & 15, ty = tid >> 4;

    const float* qp = heads + (size_t)MLEN*BSZ*QKV + b*QKV + hh*DHD;
    const float* bp = Bbase + (size_t)b*Bbst + hh*DHD;

    for (int idx = tid; idx < 4096; idx += 256) {
        int row = idx >> 6, d = idx & 63;
        Qs[d][row] = qp[(size_t)(i0+row)*(BSZ*QKV) + d] + bias[hh*DHD + d];
        Ks[d][row] = bp[(size_t)(j0+row)*Brow + d];
    }
    __syncthreads();

    float acc[4][4] = {};
    #pragma unroll
    for (int kk = 0; kk < 64; kk++) {
        float a[4], bb[4];
        #pragma unroll
        for (int i = 0; i < 4; i++) a[i] = Qs[kk][ty*4+i];
        #pragma unroll
        for (int j = 0; j < 4; j++) bb[j] = Ks[kk][tx*4+j];
        #pragma unroll
        for (int i = 0; i < 4; i++)
            #pragma unroll
            for (int j = 0; j < 4; j++)
                acc[i][j] += a[i]*bb[j];
    }
    float* op = out + (size_t)bh*QLEN*KLEN + (size_t)(i0 + ty*4)*KLEN + j0 + tx*4;
    #pragma unroll
    for (int i = 0; i < 4; i++)
        #pragma unroll
        for (int j = 0; j < 4; j++)
            op[(size_t)i*KLEN + j] = acc[i][j];
}

// ---------------- rel-shift + mask + softmax (in place over g_ac) ----------------
// score[i][j] = (AC[i][j] + BDraw[i][j + MLEN - 1 - i]) * scale   for j <= i+MLEN, else -inf
__global__ __launch_bounds__(256)
void k_softmax(const float* __restrict__ bd, float* __restrict__ ac)
{
    int i  = blockIdx.x;
    int bh = blockIdx.y;
    int tid = threadIdx.x;
    __shared__ float red[256];

    float* row = ac + (size_t)bh*QLEN*KLEN + (size_t)i*KLEN;
    const float* bdrow = bd + (size_t)bh*QLEN*KLEN + (size_t)i*KLEN;

    float sv[8];
    float mx = -1e30f;
    #pragma unroll
    for (int it = 0; it < 8; it++) {
        int j = tid + it*256;
        float s;
        if (j <= i + MLEN) {
            s = (row[j] + bdrow[j + MLEN - 1 - i]) * 0.125f;   // 1/sqrt(64)
        } else {
            s = -1e30f;
        }
        sv[it] = s;
        mx = fmaxf(mx, s);
    }
    red[tid] = mx; __syncthreads();
    for (int off = 128; off > 0; off >>= 1) {
        if (tid < off) red[tid] = fmaxf(red[tid], red[tid+off]);
        __syncthreads();
    }
    mx = red[0]; __syncthreads();

    float sum = 0.f;
    #pragma unroll
    for (int it = 0; it < 8; it++) {
        float e = expf(sv[it] - mx);
        sv[it] = e;
        sum += e;
    }
    red[tid] = sum; __syncthreads();
    for (int off = 128; off > 0; off >>= 1) {
        if (tid < off) red[tid] += red[tid+off];
        __syncthreads();
    }
    float inv = 1.0f / red[0];
    #pragma unroll
    for (int it = 0; it < 8; it++)
        row[tid + it*256] = sv[it] * inv;
}

// ---------------- PV: vec[i][b][h*64+d] = sum_j prob[bh][i][j] * v[j][b][h][d] ----------------
__global__ __launch_bounds__(256)
void k_attn_pv(const float* __restrict__ prob, const float* __restrict__ heads,
               float* __restrict__ vec)
{
    __shared__ float Ps[64][65];  // [jj][ii]
    __shared__ float Vs[64][65];  // [jj][dd]
    int bh = blockIdx.z, b = bh >> 3, hh = bh & 7;
    int i0 = blockIdx.x << 6;
    int tid = threadIdx.x, tx = tid & 15, ty = tid >> 4;

    const float* pr = prob + (size_t)bh*QLEN*KLEN + (size_t)i0*KLEN;
    const float* vp = heads + (size_t)b*QKV + 2*HD + hh*DHD;

    float acc[4][4] = {};
    for (int j0 = 0; j0 < KLEN; j0 += 64) {
        for (int idx = tid; idx < 4096; idx += 256) {
            int r = idx >> 6, c = idx & 63;
            Ps[c][r] = pr[(size_t)r*KLEN + j0 + c];                 // r=ii, c=jj
            Vs[r][c] = vp[(size_t)(j0 + r)*(BSZ*QKV) + c];          // r=jj, c=dd
        }
        __syncthreads();
        #pragma unroll
        for (int kk = 0; kk < 64; kk++) {
            float a[4], bb[4];
            #pragma unroll
            for (int i = 0; i < 4; i++) a[i] = Ps[kk][ty*4+i];
            #pragma unroll
            for (int j = 0; j < 4; j++) bb[j] = Vs[kk][tx*4+j];
            #pragma unroll
            for (int i = 0; i < 4; i++)
                #pragma unroll
                for (int j = 0; j < 4; j++)
                    acc[i][j] += a[i]*bb[j];
        }
        __syncthreads();
    }
    #pragma unroll
    for (int i = 0; i < 4; i++) {
        int gi = i0 + ty*4 + i;
        #pragma unroll
        for (int j = 0; j < 4; j++)
            vec[(size_t)gi*(BSZ*HD) + b*HD + hh*DHD + tx*4 + j] = acc[i][j];
    }
}

// ---------------- residual add + LayerNorm (row = 512) ----------------
__global__ __launch_bounds__(256)
void k_add_ln(float* __restrict__ h, const float* __restrict__ res,
              const float* __restrict__ g, const float* __restrict__ be)
{
    int row = blockIdx.x;
    int tid = threadIdx.x;
    __shared__ float red[256];
    __shared__ float s_mean, s_rstd;

    float* hp = h + (size_t)row*DM;
    const float* rp = res + (size_t)row*DM;

    float v0 = hp[tid]       + rp[tid];
    float v1 = hp[tid + 256] + rp[tid + 256];

    red[tid] = v0 + v1; __syncthreads();
    for (int off = 128; off > 0; off >>= 1) {
        if (tid < off) red[tid] += red[tid+off];
        __syncthreads();
    }
    if (tid == 0) s_mean = red[0] * (1.0f/512.0f);
    __syncthreads();
    float mean = s_mean;
    float d0 = v0 - mean, d1 = v1 - mean;

    red[tid] = d0*d0 + d1*d1; __syncthreads();
    for (int off = 128; off > 0; off >>= 1) {
        if (tid < off) red[tid] += red[tid+off];
        __syncthreads();
    }
    if (tid == 0) s_rstd = rsqrtf(red[0] * (1.0f/512.0f) + 1e-5f);
    __syncthreads();
    float rs = s_rstd;

    hp[tid]       = d0 * rs * g[tid]       + be[tid];
    hp[tid + 256] = d1 * rs * g[tid + 256] + be[tid + 256];
}

// ---------------- host ----------------
extern "C" void kernel_launch(void* const* d_in, const int* in_sizes, int n_in,
                              void* d_out, int out_size)
{
    const int*   x        = (const int*)  d_in[0];
    const float* mems     = (const float*)d_in[1];
    const float* emb      = (const float*)d_in[2];
    const float* qkv_w    = (const float*)d_in[3];
    const float* r_net_w  = (const float*)d_in[4];
    const float* o_w      = (const float*)d_in[5];
    const float* ln1_g    = (const float*)d_in[6];
    const float* ln1_b    = (const float*)d_in[7];
    const float* ff_w1    = (const float*)d_in[8];
    const float* ff_b1    = (const float*)d_in[9];
    const float* ff_w2    = (const float*)d_in[10];
    const float* ff_b2    = (const float*)d_in[11];
    const float* ln2_g    = (const float*)d_in[12];
    const float* ln2_b    = (const float*)d_in[13];
    const float* r_w_bias = (const float*)d_in[14];
    const float* r_r_bias = (const float*)d_in[15];
    const float* proj_w   = (const float*)d_in[16];
    const float* proj_b   = (const float*)d_in[17];
    float* out = (float*)d_out;

    float *h, *cat, *heads, *r, *rhk, *ac, *bd, *vec, *tmp, *ff;
    cudaGetSymbolAddress((void**)&h,     g_h);
    cudaGetSymbolAddress((void**)&cat,   g_cat);
    cudaGetSymbolAddress((void**)&heads, g_heads);
    cudaGetSymbolAddress((void**)&r,     g_r);
    cudaGetSymbolAddress((void**)&rhk,   g_rhk);
    cudaGetSymbolAddress((void**)&ac,    g_ac);
    cudaGetSymbolAddress((void**)&bd,    g_bd);
    cudaGetSymbolAddress((void**)&vec,   g_vec);
    cudaGetSymbolAddress((void**)&tmp,   g_tmp);
    cudaGetSymbolAddress((void**)&ff,    g_ff);

    const int NTOK = QLEN*BSZ;  // 4096 rows for token-wise GEMMs

    k_embed <<<(QLEN*BSZ*DM + 255)/256, 256>>>(x, emb, h);
    k_posemb<<<(KLEN*DM    + 255)/256, 256>>>(r);

    for (int l = 0; l < NL; l++) {
        // cat = [mems[l]; h]
        cudaMemcpyAsync(cat, mems + (size_t)l*MLEN*BSZ*DM,
                        sizeof(float)*MLEN*BSZ*DM, cudaMemcpyDeviceToDevice, 0);
        cudaMemcpyAsync(cat + MLEN*BSZ*DM, h,
                        sizeof(float)*QLEN*BSZ*DM, cudaMemcpyDeviceToDevice, 0);

        // heads[8192,1536] = cat[8192,512] * qkv_w[l]^T
        k_sgemm<<<dim3(QKV/BN, (KLEN*BSZ)/BM), 256>>>(
            cat, qkv_w + (size_t)l*QKV*DM, nullptr, heads,
            KLEN*BSZ, QKV, DM, 0);

        // r_head_k[2048,512] = r[2048,512] * r_net_w[l]^T
        k_sgemm<<<dim3(HD/BN, KLEN/BM), 256>>>(
            r, r_net_w + (size_t)l*HD*DM, nullptr, rhk,
            KLEN, HD, DM, 0);

        // AC and raw BD
        k_attn_qk<<<dim3(KLEN/64, QLEN/64, BSZ*NH), 256>>>(
            heads, heads + HD, r_w_bias, ac, BSZ*QKV, QKV);
        k_attn_qk<<<dim3(KLEN/64, QLEN/64, BSZ*NH), 256>>>(
            heads, rhk, r_r_bias, bd, HD, 0);

        // rel-shift + mask + softmax -> probs in ac
        k_softmax<<<dim3(QLEN, BSZ*NH), 256>>>(bd, ac);

        // attn_vec
        k_attn_pv<<<dim3(QLEN/64, 1, BSZ*NH), 256>>>(ac, heads, vec);

        // attn_out = vec * o_w[l]^T
        k_sgemm<<<dim3(DM/BN, NTOK/BM), 256>>>(
            vec, o_w + (size_t)l*DM*HD, nullptr, tmp,
            NTOK, DM, HD, 0);

        // h = LN(h + attn_out)
        k_add_ln<<<NTOK, 256>>>(h, tmp, ln1_g + l*DM, ln1_b + l*DM);

        // ff = relu(h * ff_w1^T + b1)
        k_sgemm<<<dim3(DI/BN, NTOK/BM), 256>>>(
            h, ff_w1 + (size_t)l*DI*DM, ff_b1 + (size_t)l*DI, ff,
            NTOK, DI, DM, 2);

        // tmp = ff * ff_w2^T + b2
        k_sgemm<<<dim3(DM/BN, NTOK/BM), 256>>>(
            ff, ff_w2 + (size_t)l*DM*DI, ff_b2 + (size_t)l*DM, tmp,
            NTOK, DM, DI, 1);

        // h = LN(h + ff_out)
        k_add_ln<<<NTOK, 256>>>(h, tmp, ln2_g + l*DM, ln2_b + l*DM);
    }

    // logits[4096,10000] = h * proj_w^T + proj_b
    k_sgemm<<<dim3((NV + BN - 1)/BN, NTOK/BM), 256>>>(
        h, proj_w, proj_b, out, NTOK, NV, DM, 1);
}

// round 3
// speedup vs baseline: 2.2456x; 2.2456x over previous
#include <cuda_runtime.h>
#include <cuda_bf16.h>
#include <math.h>
#include <stdint.h>

#define QLEN 1024
#define MLEN 1024
#define KLEN 2048
#define BSZ  4
#define NL   12
#define NH   8
#define DHD  64
#define DM   512
#define DI   2048
#define NV   10000
#define HD   512
#define QKV  1536

typedef __nv_bfloat16 bf16;
typedef long long ll;

// ---------------- scratch (device globals; no allocations) ----------------
__device__ bf16 g_qkvwh[9437184], g_qkvwl[9437184];
__device__ bf16 g_rnwh[3145728],  g_rnwl[3145728];
__device__ bf16 g_owh[3145728],   g_owl[3145728];
__device__ bf16 g_f1h[12582912],  g_f1l[12582912];
__device__ bf16 g_f2h[12582912],  g_f2l[12582912];
__device__ bf16 g_pwh[5120000],   g_pwl[5120000];

__device__ bf16 g_cath[4194304],  g_catl[4194304];
__device__ bf16 g_hdh[12582912],  g_hdl[12582912];
__device__ bf16 g_rh[1048576],    g_rl[1048576];
__device__ bf16 g_rkh[1048576],   g_rkl[1048576];
__device__ bf16 g_qwh[2097152],   g_qwl[2097152];
__device__ bf16 g_qrh[2097152],   g_qrl[2097152];
__device__ float g_ac[67108864];
__device__ float g_bd[67108864];
__device__ bf16 g_ph[67108864],   g_pl[67108864];
__device__ bf16 g_vth[4194304],   g_vtl[4194304];
__device__ bf16 g_vech[2097152],  g_vecl[2097152];
__device__ float g_h[2097152],    g_tmp[2097152];
__device__ bf16 g_hh[2097152],    g_hl[2097152];
__device__ bf16 g_ffh[8388608],   g_ffl[8388608];

// ---------------- helpers ----------------
__device__ __forceinline__ uint32_t smem_u32(const void* p){
    uint32_t a;
    asm("{ .reg .u64 t; cvta.to.shared.u64 t, %1; cvt.u32.u64 %0, t; }" : "=r"(a) : "l"(p));
    return a;
}
__device__ __forceinline__ void cpasync16(uint32_t dst, const void* src, int sz){
    asm volatile("cp.async.cg.shared.global [%0], [%1], 16, %2;"
                 :: "r"(dst), "l"(src), "r"(sz) : "memory");
}
__device__ __forceinline__ void cp_commit(){
    asm volatile("cp.async.commit_group;" ::: "memory");
}
__device__ __forceinline__ void cp_wait0(){
    asm volatile("cp.async.wait_group 0;" ::: "memory");
}
__device__ __forceinline__ void cp_wait1(){
    asm volatile("cp.async.wait_group 1;" ::: "memory");
}
__device__ __forceinline__ void mma16816(float* c, const uint32_t* a, const uint32_t* b){
    asm volatile(
        "mma.sync.aligned.m16n8k16.row.col.f32.bf16.bf16.f32 "
        "{%0,%1,%2,%3}, {%4,%5,%6,%7}, {%8,%9}, {%0,%1,%2,%3};"
        : "+f"(c[0]), "+f"(c[1]), "+f"(c[2]), "+f"(c[3])
        : "r"(a[0]), "r"(a[1]), "r"(a[2]), "r"(a[3]), "r"(b[0]), "r"(b[1]));
}
__device__ __forceinline__ void split2(float v, bf16* hi, bf16* lo){
    bf16 h = __float2bfloat16(v);
    *hi = h;
    *lo = __float2bfloat16(v - __bfloat162float(h));
}

// ================= split-bf16 mma.sync GEMM =================
// C[m,n] = sum_k A[m,k]*B[n,k], A/B as (hi,lo) bf16 pairs; 3-term compensation.
// grid: x = ceil(N/TN), y = M/128, z = batch; offsets (z/ZD)*q + (z%ZD)*r
// mode bits: 1=write fp32 Cf, 2=write split Chi/Clo, 4=+bias, 8=relu
// smem stage layout: [Ahi 128x72][Alo 128x72][Bhi TNx72][Blo TNx72] bf16, row=144B
template<int TN>
__device__ __forceinline__ void load_stage(uint32_t base,
        const bf16* __restrict__ Ah, const bf16* __restrict__ Al,
        const bf16* __restrict__ Bh, const bf16* __restrict__ Bl,
        ll lda, ll ldb, int k0, int tid, int n0, int N)
{
    const int ABYTES = 128*144;
    const int BBYTES = TN*144;
    #pragma unroll
    for (int c = tid; c < 2048; c += 256) {
        int part = c >> 10;
        int r    = (c >> 3) & 127;
        int qq   = c & 7;
        uint32_t dst = base + part*ABYTES + r*144 + qq*16;
        const bf16* src = (part ? Al : Ah) + (ll)r*lda + k0 + qq*8;
        cpasync16(dst, src, 16);
    }
    #pragma unroll
    for (int c = tid; c < TN*16; c += 256) {
        int part = c / (TN*8);
        int r    = (c >> 3) % TN;
        int qq   = c & 7;
        uint32_t dst = base + 2*ABYTES + part*BBYTES + r*144 + qq*16;
        int ok = (n0 + r < N) ? 16 : 0;
        const bf16* src = (part ? Bl : Bh) + (ok ? ((ll)r*ldb + k0 + qq*8) : 0);
        cpasync16(dst, src, ok);
    }
    cp_commit();
}

template<int TN>
__global__ void __launch_bounds__(256, 1)
k_gemm(const bf16* __restrict__ Ahi, const bf16* __restrict__ Alo, ll lda, ll aq, ll ar,
       const bf16* __restrict__ Bhi, const bf16* __restrict__ Blo, ll ldb, ll bq, ll br,
       float* __restrict__ Cf, bf16* __restrict__ Chi, bf16* __restrict__ Clo, ll ldc, ll cq, ll cr,
       const float* __restrict__ bias, int N, int K, int ZD, int mode)
{
    extern __shared__ char dsm[];
    const int ABYTES = 128*144;
    const int BBYTES = TN*144;
    const int STG    = 2*ABYTES + 2*BBYTES;
    const int NT     = TN/32;      // n8 tiles per warp

    uint32_t sb = smem_u32(dsm);
    int tid  = threadIdx.x;
    int wid  = tid >> 5, lane = tid & 31;
    int wm   = wid >> 2;           // 0..1 -> 64 rows each
    int wn   = wid & 3;            // 0..3 -> TN/4 cols each
    int tg   = lane >> 2, tq = lane & 3;

    int z  = blockIdx.z;
    int m0 = blockIdx.y << 7;
    int n0 = blockIdx.x * TN;
    ll offA = (ll)(z / ZD) * aq + (ll)(z % ZD) * ar;
    ll offB = (ll)(z / ZD) * bq + (ll)(z % ZD) * br;
    ll offC = (ll)(z / ZD) * cq + (ll)(z % ZD) * cr;

    const bf16* Ah = Ahi + offA + (ll)m0 * lda;
    const bf16* Al = Alo + offA + (ll)m0 * lda;
    const bf16* Bh = Bhi + offB + (ll)n0 * ldb;
    const bf16* Bl = Blo + offB + (ll)n0 * ldb;

    float acc[4][NT][4];
    #pragma unroll
    for (int i = 0; i < 4; i++)
        #pragma unroll
        for (int j = 0; j < NT; j++)
            #pragma unroll
            for (int r = 0; r < 4; r++) acc[i][j][r] = 0.f;

    int nKb = K >> 6;
    load_stage<TN>(sb, Ah, Al, Bh, Bl, lda, ldb, 0, tid, n0, N);

    for (int kb = 0; kb < nKb; kb++) {
        if (kb + 1 < nKb) {
            load_stage<TN>(sb + ((kb+1)&1)*STG, Ah, Al, Bh, Bl, lda, ldb,
                           (kb+1) << 6, tid, n0, N);
            cp_wait1();
        } else {
            cp_wait0();
        }
        __syncthreads();

        const uint32_t* As = (const uint32_t*)(dsm + (kb&1)*STG);               // hi
        const uint32_t* Bs = (const uint32_t*)(dsm + (kb&1)*STG + 2*ABYTES);    // hi
        const int AP = ABYTES/4, BP = BBYTES/4;  // part offsets in words

        #pragma unroll
        for (int kk = 0; kk < 4; kk++) {
            uint32_t a_h[4][4], a_l[4][4], b_h[NT][2], b_l[NT][2];
            int kw = kk*8 + tq;   // word col
            #pragma unroll
            for (int mt = 0; mt < 4; mt++) {
                int r0 = (wm*64 + mt*16 + tg) * 36;
                int r1 = r0 + 8*36;
                a_h[mt][0] = As[r0 + kw];      a_h[mt][1] = As[r1 + kw];
                a_h[mt][2] = As[r0 + kw + 4];  a_h[mt][3] = As[r1 + kw + 4];
                a_l[mt][0] = As[AP + r0 + kw];     a_l[mt][1] = As[AP + r1 + kw];
                a_l[mt][2] = As[AP + r0 + kw + 4]; a_l[mt][3] = As[AP + r1 + kw + 4];
            }
            #pragma unroll
            for (int nt = 0; nt < NT; nt++) {
                int nr = (wn*(TN/4) + nt*8 + tg) * 36;
                b_h[nt][0] = Bs[nr + kw];      b_h[nt][1] = Bs[nr + kw + 4];
                b_l[nt][0] = Bs[BP + nr + kw]; b_l[nt][1] = Bs[BP + nr + kw + 4];
            }
            #pragma unroll
            for (int mt = 0; mt < 4; mt++)
                #pragma unroll
                for (int nt = 0; nt < NT; nt++) {
                    mma16816(acc[mt][nt], a_h[mt], b_h[nt]);
                    mma16816(acc[mt][nt], a_h[mt], b_l[nt]);
                    mma16816(acc[mt][nt], a_l[mt], b_h[nt]);
                }
        }
        __syncthreads();
    }

    // epilogue
    #pragma unroll
    for (int mt = 0; mt < 4; mt++) {
        #pragma unroll
        for (int nt = 0; nt < NT; nt++) {
            #pragma unroll
            for (int r = 0; r < 4; r++) {
                int m = m0 + wm*64 + mt*16 + tg + ((r >= 2) ? 8 : 0);
                int n = n0 + wn*(TN/4) + nt*8 + tq*2 + (r & 1);
                if (n >= N) continue;
                float v = acc[mt][nt][r];
                if (mode & 4) v += bias[n];
                if (mode & 8) v = fmaxf(v, 0.f);
                ll cidx = offC + (ll)m * ldc + n;
                if (mode & 1) Cf[cidx] = v;
                if (mode & 2) {
                    bf16 hh = __float2bfloat16(v);
                    Chi[cidx] = hh;
                    Clo[cidx] = __float2bfloat16(v - __bfloat162float(hh));
                }
            }
        }
    }
}

// ================= elementwise / small kernels =================
__global__ void k_split(const float* __restrict__ in, bf16* __restrict__ hi,
                        bf16* __restrict__ lo, ll n){
    ll i = (ll)blockIdx.x * blockDim.x + threadIdx.x;
    if (i >= n) return;
    split2(in[i], hi + i, lo + i);
}

__global__ void k_embed(const int* __restrict__ x, const float* __restrict__ emb,
                        float* __restrict__ h, bf16* __restrict__ hh, bf16* __restrict__ hl)
{
    int idx = blockIdx.x * blockDim.x + threadIdx.x;
    if (idx >= QLEN*BSZ*DM) return;
    int d = idx & (DM-1);
    int b = (idx >> 9) & 3;
    int i = idx >> 11;
    int tok = x[i*BSZ + b];
    float v = emb[(ll)tok*DM + d] * 22.627416997969522f;
    h[idx] = v;
    split2(v, hh + idx, hl + idx);
}

__global__ void k_posemb(bf16* __restrict__ rh, bf16* __restrict__ rl)
{
    int idx = blockIdx.x * blockDim.x + threadIdx.x;
    if (idx >= KLEN*DM) return;
    int d = idx & (DM-1);
    int k = idx >> 9;
    double pos = (double)(KLEN - 1 - k);
    int t = (d < 256) ? d : d - 256;
    double f = exp(-(double)t * (log(10000.0) / 256.0));
    double a = pos * f;
    float v = (float)((d < 256) ? sin(a) : cos(a));
    split2(v, rh + idx, rl + idx);
}

__global__ void k_cat(const float* __restrict__ mems_l, const bf16* __restrict__ hh,
                      const bf16* __restrict__ hl, bf16* __restrict__ ch, bf16* __restrict__ cl)
{
    ll i = (ll)blockIdx.x * blockDim.x + threadIdx.x;
    const ll msz = (ll)MLEN*BSZ*DM;
    if (i < msz) {
        split2(mems_l[i], ch + i, cl + i);
    } else if (i < msz + (ll)QLEN*BSZ*DM) {
        ch[i] = hh[i - msz];
        cl[i] = hl[i - msz];
    }
}

// q + biases, re-split into [bh][i][64]
__global__ void k_qbias(const bf16* __restrict__ hh, const bf16* __restrict__ hl,
                        const float* __restrict__ rwb, const float* __restrict__ rrb,
                        bf16* __restrict__ qwh, bf16* __restrict__ qwl,
                        bf16* __restrict__ qrh, bf16* __restrict__ qrl)
{
    int idx = blockIdx.x * blockDim.x + threadIdx.x;
    if (idx >= 32*1024*64) return;
    int d = idx & 63;
    int i = (idx >> 6) & 1023;
    int z = idx >> 16;
    int b = z >> 3, h_ = z & 7;
    ll src = ((ll)(MLEN + i)*BSZ + b)*QKV + h_*64 + d;
    float q = __bfloat162float(hh[src]) + __bfloat162float(hl[src]);
    split2(q + rwb[h_*64 + d], qwh + idx, qwl + idx);
    split2(q + rrb[h_*64 + d], qrh + idx, qrl + idx);
}

// V transpose into [bh][d][j]
__global__ void k_vtrans(const bf16* __restrict__ hh, const bf16* __restrict__ hl,
                         bf16* __restrict__ vth, bf16* __restrict__ vtl)
{
    __shared__ bf16 th[64][65], tl[64][65];
    int z = blockIdx.y;
    int j0 = blockIdx.x << 6;
    int b = z >> 3, h_ = z & 7;
    #pragma unroll
    for (int p = 0; p < 16; p++) {
        int jj = (threadIdx.x >> 6) + p*4;
        int d  = threadIdx.x & 63;
        ll src = ((ll)(j0 + jj)*BSZ + b)*QKV + 1024 + h_*64 + d;
        th[jj][d] = hh[src];
        tl[jj][d] = hl[src];
    }
    __syncthreads();
    #pragma unroll
    for (int p = 0; p < 16; p++) {
        int dd = (threadIdx.x >> 6) + p*4;
        int j  = threadIdx.x & 63;
        ll dst = (ll)z*131072 + (ll)dd*2048 + j0 + j;
        vth[dst] = th[j][dd];
        vtl[dst] = tl[j][dd];
    }
}

// rel-shift + mask + softmax -> split probs
__global__ void __launch_bounds__(256)
k_softmax(const float* __restrict__ bd, const float* __restrict__ ac,
          bf16* __restrict__ ph, bf16* __restrict__ pl)
{
    int i  = blockIdx.x;
    int bh = blockIdx.y;
    int tid = threadIdx.x;
    __shared__ float red[256];

    const float* row   = ac + (ll)bh*QLEN*KLEN + (ll)i*KLEN;
    const float* bdrow = bd + (ll)bh*QLEN*KLEN + (ll)i*KLEN;
    bf16* prh = ph + (ll)bh*QLEN*KLEN + (ll)i*KLEN;
    bf16* prl = pl + (ll)bh*QLEN*KLEN + (ll)i*KLEN;

    float sv[8];
    float mx = -1e30f;
    #pragma unroll
    for (int it = 0; it < 8; it++) {
        int j = tid + it*256;
        float s;
        if (j <= i + MLEN) s = (row[j] + bdrow[j + MLEN - 1 - i]) * 0.125f;
        else s = -1e30f;
        sv[it] = s;
        mx = fmaxf(mx, s);
    }
    red[tid] = mx; __syncthreads();
    for (int off = 128; off > 0; off >>= 1) {
        if (tid < off) red[tid] = fmaxf(red[tid], red[tid+off]);
        __syncthreads();
    }
    mx = red[0]; __syncthreads();

    float sum = 0.f;
    #pragma unroll
    for (int it = 0; it < 8; it++) {
        float e = expf(sv[it] - mx);
        sv[it] = e;
        sum += e;
    }
    red[tid] = sum; __syncthreads();
    for (int off = 128; off > 0; off >>= 1) {
        if (tid < off) red[tid] += red[tid+off];
        __syncthreads();
    }
    float inv = 1.0f / red[0];
    #pragma unroll
    for (int it = 0; it < 8; it++) {
        int j = tid + it*256;
        float p = sv[it] * inv;
        bf16 h_ = __float2bfloat16(p);
        prh[j] = h_;
        prl[j] = __float2bfloat16(p - __bfloat162float(h_));
    }
}

__global__ void __launch_bounds__(256)
k_add_ln(float* __restrict__ h, const float* __restrict__ res,
         const float* __restrict__ g, const float* __restrict__ be,
         bf16* __restrict__ hh, bf16* __restrict__ hl)
{
    int row = blockIdx.x;
    int tid = threadIdx.x;
    __shared__ float red[256];
    __shared__ float s_mean, s_rstd;

    float* hp = h + (ll)row*DM;
    const float* rp = res + (ll)row*DM;

    float v0 = hp[tid]       + rp[tid];
    float v1 = hp[tid + 256] + rp[tid + 256];

    red[tid] = v0 + v1; __syncthreads();
    for (int off = 128; off > 0; off >>= 1) {
        if (tid < off) red[tid] += red[tid+off];
        __syncthreads();
    }
    if (tid == 0) s_mean = red[0] * (1.0f/512.0f);
    __syncthreads();
    float mean = s_mean;
    float d0 = v0 - mean, d1 = v1 - mean;

    red[tid] = d0*d0 + d1*d1; __syncthreads();
    for (int off = 128; off > 0; off >>= 1) {
        if (tid < off) red[tid] += red[tid+off];
        __syncthreads();
    }
    if (tid == 0) s_rstd = rsqrtf(red[0] * (1.0f/512.0f) + 1e-5f);
    __syncthreads();
    float rs = s_rstd;

    float o0 = d0 * rs * g[tid]       + be[tid];
    float o1 = d1 * rs * g[tid + 256] + be[tid + 256];
    hp[tid]       = o0;
    hp[tid + 256] = o1;
    ll base = (ll)row*DM;
    split2(o0, hh + base + tid,       hl + base + tid);
    split2(o1, hh + base + tid + 256, hl + base + tid + 256);
}

// ================= host =================
static const int SM128 = 2*(2*128*144 + 2*128*144);   // 147456
static const int SM64  = 2*(2*128*144 + 2*64*144);    // 110592

extern "C" void kernel_launch(void* const* d_in, const int* in_sizes, int n_in,
                              void* d_out, int out_size)
{
    const int*   x        = (const int*)  d_in[0];
    const float* mems     = (const float*)d_in[1];
    const float* emb      = (const float*)d_in[2];
    const float* qkv_w    = (const float*)d_in[3];
    const float* r_net_w  = (const float*)d_in[4];
    const float* o_w      = (const float*)d_in[5];
    const float* ln1_g    = (const float*)d_in[6];
    const float* ln1_b    = (const float*)d_in[7];
    const float* ff_w1    = (const float*)d_in[8];
    const float* ff_b1    = (const float*)d_in[9];
    const float* ff_w2    = (const float*)d_in[10];
    const float* ff_b2    = (const float*)d_in[11];
    const float* ln2_g    = (const float*)d_in[12];
    const float* ln2_b    = (const float*)d_in[13];
    const float* r_w_bias = (const float*)d_in[14];
    const float* r_r_bias = (const float*)d_in[15];
    const float* proj_w   = (const float*)d_in[16];
    const float* proj_b   = (const float*)d_in[17];
    float* out = (float*)d_out;

    static bool attr_done = false;
    if (!attr_done) {
        cudaFuncSetAttribute(k_gemm<128>, cudaFuncAttributeMaxDynamicSharedMemorySize, SM128);
        cudaFuncSetAttribute(k_gemm<64>,  cudaFuncAttributeMaxDynamicSharedMemorySize, SM64);
        attr_done = true;
    }

    bf16 *qkvwh,*qkvwl,*rnwh,*rnwl,*owh,*owl,*f1h,*f1l,*f2h,*f2l,*pwh,*pwl;
    bf16 *cath,*catl,*hdh,*hdl,*rh,*rl,*rkh,*rkl,*qwh,*qwl,*qrh,*qrl;
    bf16 *ph_,*pl_,*vth,*vtl,*vech,*vecl,*hh,*hl,*ffh,*ffl;
    float *ac,*bd,*h,*tmp;
    cudaGetSymbolAddress((void**)&qkvwh, g_qkvwh); cudaGetSymbolAddress((void**)&qkvwl, g_qkvwl);
    cudaGetSymbolAddress((void**)&rnwh,  g_rnwh);  cudaGetSymbolAddress((void**)&rnwl,  g_rnwl);
    cudaGetSymbolAddress((void**)&owh,   g_owh);   cudaGetSymbolAddress((void**)&owl,   g_owl);
    cudaGetSymbolAddress((void**)&f1h,   g_f1h);   cudaGetSymbolAddress((void**)&f1l,   g_f1l);
    cudaGetSymbolAddress((void**)&f2h,   g_f2h);   cudaGetSymbolAddress((void**)&f2l,   g_f2l);
    cudaGetSymbolAddress((void**)&pwh,   g_pwh);   cudaGetSymbolAddress((void**)&pwl,   g_pwl);
    cudaGetSymbolAddress((void**)&cath,  g_cath);  cudaGetSymbolAddress((void**)&catl,  g_catl);
    cudaGetSymbolAddress((void**)&hdh,   g_hdh);   cudaGetSymbolAddress((void**)&hdl,   g_hdl);
    cudaGetSymbolAddress((void**)&rh,    g_rh);    cudaGetSymbolAddress((void**)&rl,    g_rl);
    cudaGetSymbolAddress((void**)&rkh,   g_rkh);   cudaGetSymbolAddress((void**)&rkl,   g_rkl);
    cudaGetSymbolAddress((void**)&qwh,   g_qwh);   cudaGetSymbolAddress((void**)&qwl,   g_qwl);
    cudaGetSymbolAddress((void**)&qrh,   g_qrh);   cudaGetSymbolAddress((void**)&qrl,   g_qrl);
    cudaGetSymbolAddress((void**)&ph_,   g_ph);    cudaGetSymbolAddress((void**)&pl_,   g_pl);
    cudaGetSymbolAddress((void**)&vth,   g_vth);   cudaGetSymbolAddress((void**)&vtl,   g_vtl);
    cudaGetSymbolAddress((void**)&vech,  g_vech);  cudaGetSymbolAddress((void**)&vecl,  g_vecl);
    cudaGetSymbolAddress((void**)&hh,    g_hh);    cudaGetSymbolAddress((void**)&hl,    g_hl);
    cudaGetSymbolAddress((void**)&ffh,   g_ffh);   cudaGetSymbolAddress((void**)&ffl,   g_ffl);
    cudaGetSymbolAddress((void**)&ac,    g_ac);    cudaGetSymbolAddress((void**)&bd,    g_bd);
    cudaGetSymbolAddress((void**)&h,     g_h);     cudaGetSymbolAddress((void**)&tmp,   g_tmp);

    // split all weights
    k_split<<<(9437184 +255)/256, 256>>>(qkv_w,   qkvwh, qkvwl, 9437184LL);
    k_split<<<(3145728 +255)/256, 256>>>(r_net_w, rnwh,  rnwl,  3145728LL);
    k_split<<<(3145728 +255)/256, 256>>>(o_w,     owh,   owl,   3145728LL);
    k_split<<<(12582912+255)/256, 256>>>(ff_w1,   f1h,   f1l,   12582912LL);
    k_split<<<(12582912+255)/256, 256>>>(ff_w2,   f2h,   f2l,   12582912LL);
    k_split<<<(5120000 +255)/256, 256>>>(proj_w,  pwh,   pwl,   5120000LL);

    const int NTOK = QLEN*BSZ;
    k_embed <<<(QLEN*BSZ*DM + 255)/256, 256>>>(x, emb, h, hh, hl);
    k_posemb<<<(KLEN*DM + 255)/256, 256>>>(rh, rl);

    for (int l = 0; l < NL; l++) {
        k_cat<<<(KLEN*BSZ*DM + 255)/256, 256>>>(mems + (ll)l*MLEN*BSZ*DM, hh, hl, cath, catl);

        // heads = cat x qkv_w^T  -> split
        k_gemm<128><<<dim3(12, 64, 1), 256, SM128>>>(
            cath, catl, 512, 0, 0,
            qkvwh + (ll)l*786432, qkvwl + (ll)l*786432, 512, 0, 0,
            nullptr, hdh, hdl, 1536, 0, 0,
            nullptr, 1536, 512, 1, 2);

        // rhk = r x r_net_w^T -> split
        k_gemm<128><<<dim3(4, 16, 1), 256, SM128>>>(
            rh, rl, 512, 0, 0,
            rnwh + (ll)l*262144, rnwl + (ll)l*262144, 512, 0, 0,
            nullptr, rkh, rkl, 512, 0, 0,
            nullptr, 512, 512, 1, 2);

        // q + biases
        k_qbias<<<(32*1024*64 + 255)/256, 256>>>(hdh, hdl, r_w_bias, r_r_bias, qwh, qwl, qrh, qrl);

        // AC[bh][i][j]
        k_gemm<128><<<dim3(16, 8, 32), 256, SM128>>>(
            qwh, qwl, 64, 8LL*65536, 65536,
            hdh + 512, hdl + 512, 6144, 1536, 64,
            ac, nullptr, nullptr, 2048, 8LL*2097152, 2097152,
            nullptr, 2048, 64, 8, 1);

        // BD raw
        k_gemm<128><<<dim3(16, 8, 32), 256, SM128>>>(
            qrh, qrl, 64, 8LL*65536, 65536,
            rkh, rkl, 512, 0, 64,
            bd, nullptr, nullptr, 2048, 8LL*2097152, 2097152,
            nullptr, 2048, 64, 8, 1);

        // softmax -> split probs
        k_softmax<<<dim3(QLEN, 32), 256>>>(bd, ac, ph_, pl_);

        // V transpose
        k_vtrans<<<dim3(32, 32), 256>>>(hdh, hdl, vth, vtl);

        // PV: vec[i][b][h*64+d]  -> split
        k_gemm<64><<<dim3(1, 8, 32), 256, SM64>>>(
            ph_, pl_, 2048, 8LL*2097152, 2097152,
            vth, vtl, 2048, 8LL*131072, 131072,
            nullptr, vech, vecl, 2048, 512, 64,
            nullptr, 64, 2048, 8, 2);

        // attn_out = vec x o_w^T -> fp32 tmp
        k_gemm<128><<<dim3(4, 32, 1), 256, SM128>>>(
            vech, vecl, 512, 0, 0,
            owh + (ll)l*262144, owl + (ll)l*262144, 512, 0, 0,
            tmp, nullptr, nullptr, 512, 0, 0,
            nullptr, 512, 512, 1, 1);

        k_add_ln<<<NTOK, 256>>>(h, tmp, ln1_g + l*DM, ln1_b + l*DM, hh, hl);

        // ff = relu(h x ff_w1^T + b1) -> split
        k_gemm<128><<<dim3(16, 32, 1), 256, SM128>>>(
            hh, hl, 512, 0, 0,
            f1h + (ll)l*1048576, f1l + (ll)l*1048576, 512, 0, 0,
            nullptr, ffh, ffl, 2048, 0, 0,
            ff_b1 + (ll)l*DI, 2048, 512, 1, 2|4|8);

        // tmp = ff x ff_w2^T + b2 -> fp32
        k_gemm<128><<<dim3(4, 32, 1), 256, SM128>>>(
            ffh, ffl, 2048, 0, 0,
            f2h + (ll)l*1048576, f2l + (ll)l*1048576, 2048, 0, 0,
            tmp, nullptr, nullptr, 512, 0, 0,
            ff_b2 + (ll)l*DM, 512, 2048, 1, 1|4);

        k_add_ln<<<NTOK, 256>>>(h, tmp, ln2_g + l*DM, ln2_b + l*DM, hh, hl);
    }

    // logits = h x proj_w^T + proj_b  (N tail via predication + zero-fill)
    k_gemm<128><<<dim3(79, 32, 1), 256, SM128>>>(
        hh, hl, 512, 0, 0,
        pwh, pwl, 512, 0, 0,
        out, nullptr, nullptr, 10000, 0, 0,
        proj_b, 10000, 512, 1, 1|4);
}